// round 1
// baseline (speedup 1.0000x reference)
#include <cuda_runtime.h>
#include <cuda_bf16.h>
#include <math.h>

// Problem constants
#define BB   8
#define HH   128
#define WW   128
#define CIN  64
#define GG   2
#define GCH  32      // channels per group
#define SCH  288     // K*K*GC
#define GF   64      // filters per group
#define NP   (BB*HH*WW)   // 131072 pixels

// Scratch: sampled field, [g][pixel][288]  (302 MB)
__device__ float g_samp[(size_t)GG * NP * SCH];

// ---------------------------------------------------------------------------
// Kernel 1: offset conv + bilinear sampling.
// One warp per (pixel, group). lane = channel (0..31).
// ---------------------------------------------------------------------------
__global__ __launch_bounds__(256) void k_sample(
    const float* __restrict__ x,      // [B,H,W,64]
    const float* __restrict__ off_w,  // [G,3,3,32,18]
    const float* __restrict__ off_b)  // [G,18]
{
    __shared__ float ws[18 * 288];    // transposed: ws[j*288 + t*32 + c]
    __shared__ float wb[18];

    const int g   = blockIdx.y;
    const int tid = threadIdx.x;

    for (int i = tid; i < 18 * 288; i += 256) {
        int j = i / 288, r = i % 288;              // r = t*32 + c
        ws[i] = off_w[(size_t)(g * 288 + r) * 18 + j];
    }
    if (tid < 18) wb[tid] = off_b[g * 18 + tid];
    __syncthreads();

    const int warp = tid >> 5, lane = tid & 31;
    const int p   = blockIdx.x * 8 + warp;         // pixel index
    const int b   = p >> 14;
    const int rem = p & 16383;
    const int yy  = rem >> 7;
    const int xx  = rem & 127;

    // 3x3 neighborhood of this pixel, channel = lane (coalesced loads)
    float xv[9];
#pragma unroll
    for (int t = 0; t < 9; t++) {
        int ny = yy + t / 3 - 1, nx = xx + t % 3 - 1;
        xv[t] = (ny >= 0 && ny < HH && nx >= 0 && nx < WW)
              ? x[((size_t)((b * HH + ny) * WW + nx)) * CIN + g * GCH + lane]
              : 0.f;
    }

    // Offset conv: per-lane partials over this lane's channel, then butterfly sum
    float po[18];
#pragma unroll
    for (int j = 0; j < 18; j++) po[j] = 0.f;
#pragma unroll
    for (int t = 0; t < 9; t++) {
        const float v = xv[t];
        const float* wr = &ws[t * 32 + lane];
#pragma unroll
        for (int j = 0; j < 18; j++) po[j] = fmaf(v, wr[j * 288], po[j]);
    }
#pragma unroll
    for (int s = 16; s > 0; s >>= 1) {
#pragma unroll
        for (int j = 0; j < 18; j++)
            po[j] += __shfl_xor_sync(0xffffffffu, po[j], s);
    }
#pragma unroll
    for (int j = 0; j < 18; j++) po[j] += wb[j];

    // 9 bilinear samples, channel = lane. Replicate reference's clip/floor math
    // exactly (including the zero-result edge case at coord == 127.0).
    const size_t xbase = (size_t)b * (HH * WW) * CIN + g * GCH + lane;
    float* outp = &g_samp[((size_t)g * NP + p) * SCH + lane];
#pragma unroll
    for (int k = 0; k < 9; k++) {
        float lx = (float)xx + (float)(k % 3 - 1) + po[2 * k];
        float ly = (float)yy + (float)(k / 3 - 1) + po[2 * k + 1];
        lx = fminf(fmaxf(lx, 0.f), 127.f);
        ly = fminf(fmaxf(ly, 0.f), 127.f);
        float x0f = fminf(fmaxf(floorf(lx), 0.f), 127.f);
        float y0f = fminf(fmaxf(floorf(ly), 0.f), 127.f);
        float x1f = fminf(x0f + 1.f, 127.f);
        float y1f = fminf(y0f + 1.f, 127.f);
        int x0 = (int)x0f, x1 = (int)x1f, y0 = (int)y0f, y1 = (int)y1f;
        float dx1 = x1f - lx, dx0 = lx - x0f;
        float dy1 = y1f - ly, dy0 = ly - y0f;
        float Ia = x[xbase + (size_t)(y0 * WW + x0) * CIN];   // (y0,x0)
        float Ib = x[xbase + (size_t)(y1 * WW + x0) * CIN];   // (y1,x0)
        float Ic = x[xbase + (size_t)(y0 * WW + x1) * CIN];   // (y0,x1)
        float Id = x[xbase + (size_t)(y1 * WW + x1) * CIN];   // (y1,x1)
        outp[k * 32] = dx1 * dy1 * Ia + dx1 * dy0 * Ib
                     + dx0 * dy1 * Ic + dx0 * dy0 * Id;
    }
}

// ---------------------------------------------------------------------------
// Kernel 2: fused depthwise(3x3, groups=288) + pointwise(288->64).
// One block per 8x8 pixel tile per (b,g). 512 threads.
// smem: [samp halo 10*10*288 | y 64*288 | dw 9*288], halo region reused for pw.
// ---------------------------------------------------------------------------
#define SM_TILE 28800    // 10*10*288 floats
#define SM_Y    18432    // 64*288 floats
#define SM_DW   2592     // 9*288 floats
#define SM_TOTAL_BYTES ((SM_TILE + SM_Y + SM_DW) * 4)

__global__ __launch_bounds__(512) void k_dwpw(
    const float* __restrict__ dw_w,   // [G,3,3,288,1]
    const float* __restrict__ dw_b,   // [G,288]
    const float* __restrict__ pw_w,   // [G,1,1,288,64]
    const float* __restrict__ pw_b,   // [G,64]
    float* __restrict__ out)          // [B,H,W,128]
{
    extern __shared__ float smem[];
    float* s_tile = smem;                       // halo tile, then pw weights
    float* s_y    = smem + SM_TILE;
    float* s_dw   = smem + SM_TILE + SM_Y;

    const int tid = threadIdx.x;
    const int z   = blockIdx.z;
    const int g   = z & 1;
    const int b   = z >> 1;
    const int ty0 = blockIdx.y * 8;
    const int tx0 = blockIdx.x * 8;

    // --- Stage samp halo (10x10 x 288) as float4 ---
    float4* t4 = (float4*)s_tile;
    for (int i = tid; i < 7200; i += 512) {
        int hp = i / 72, c4 = i % 72;
        int hy = ty0 + hp / 10 - 1, hx = tx0 + hp % 10 - 1;
        float4 v = make_float4(0.f, 0.f, 0.f, 0.f);
        if (hy >= 0 && hy < HH && hx >= 0 && hx < WW)
            v = *(const float4*)&g_samp[((size_t)g * NP +
                    (size_t)((b * HH + hy) * WW + hx)) * SCH + c4 * 4];
        t4[i] = v;
    }
    float4* d4 = (float4*)s_dw;
    for (int i = tid; i < 648; i += 512)
        d4[i] = __ldg((const float4*)&dw_w[(size_t)g * 2592 + i * 4]);
    __syncthreads();

    // --- Depthwise 3x3 (zero-padded SAME), vectorized over channels ---
    float4* y4 = (float4*)s_y;
    for (int i = tid; i < 4608; i += 512) {
        int p = i / 72, c4 = i % 72;
        int py = p >> 3, px = p & 7;
        float4 acc = __ldg((const float4*)&dw_b[g * SCH + c4 * 4]);
#pragma unroll
        for (int t = 0; t < 9; t++) {
            float4 w = d4[t * 72 + c4];
            float4 v = t4[((py + t / 3) * 10 + (px + t % 3)) * 72 + c4];
            acc.x = fmaf(w.x, v.x, acc.x);
            acc.y = fmaf(w.y, v.y, acc.y);
            acc.z = fmaf(w.z, v.z, acc.z);
            acc.w = fmaf(w.w, v.w, acc.w);
        }
        y4[i] = acc;
    }
    __syncthreads();

    // --- Reuse halo region for pointwise weights [c][f] ---
    for (int i = tid; i < 4608; i += 512)
        t4[i] = __ldg((const float4*)&pw_w[(size_t)g * (SCH * GF) + i * 4]);
    __syncthreads();

    // --- Pointwise 288 -> 64. thread: f = tid&63, 8 pixels (p = pq + 8*i) ---
    const int f  = tid & 63;
    const int pq = tid >> 6;               // 0..7, warp-uniform
    float acc[8];
    const float bias = __ldg(&pw_b[g * GF + f]);
#pragma unroll
    for (int i = 0; i < 8; i++) acc[i] = bias;

    for (int c4 = 0; c4 < 72; c4++) {
        float w0 = s_tile[(4 * c4 + 0) * 64 + f];
        float w1 = s_tile[(4 * c4 + 1) * 64 + f];
        float w2 = s_tile[(4 * c4 + 2) * 64 + f];
        float w3 = s_tile[(4 * c4 + 3) * 64 + f];
#pragma unroll
        for (int i = 0; i < 8; i++) {
            float4 yv = y4[(pq + i * 8) * 72 + c4];   // smem broadcast
            acc[i] = fmaf(yv.x, w0, acc[i]);
            acc[i] = fmaf(yv.y, w1, acc[i]);
            acc[i] = fmaf(yv.z, w2, acc[i]);
            acc[i] = fmaf(yv.w, w3, acc[i]);
        }
    }
#pragma unroll
    for (int i = 0; i < 8; i++) {
        int p = pq + i * 8;
        int py = p >> 3, px = p & 7;
        out[((size_t)((b * HH + ty0 + py) * WW) + tx0 + px) * (GG * GF)
            + g * GF + f] = acc[i];
    }
}

// ---------------------------------------------------------------------------
extern "C" void kernel_launch(void* const* d_in, const int* in_sizes, int n_in,
                              void* d_out, int out_size)
{
    const float* x     = (const float*)d_in[0];
    const float* off_w = (const float*)d_in[1];
    const float* off_b = (const float*)d_in[2];
    const float* dw_w  = (const float*)d_in[3];
    const float* dw_b  = (const float*)d_in[4];
    const float* pw_w  = (const float*)d_in[5];
    const float* pw_b  = (const float*)d_in[6];
    float* out = (float*)d_out;

    cudaFuncSetAttribute(k_dwpw, cudaFuncAttributeMaxDynamicSharedMemorySize,
                         SM_TOTAL_BYTES);

    k_sample<<<dim3(NP / 8, GG), 256>>>(x, off_w, off_b);
    k_dwpw<<<dim3(WW / 8, HH / 8, BB * GG), 512, SM_TOTAL_BYTES>>>(
        dw_w, dw_b, pw_w, pw_b, out);
}

// round 2
// speedup vs baseline: 1.1265x; 1.1265x over previous
#include <cuda_runtime.h>
#include <cuda_bf16.h>
#include <math.h>

// Problem constants
#define BB   8
#define HH   128
#define WW   128
#define CIN  64
#define GG   2
#define GCH  32      // channels per group
#define SCH  288     // K*K*GC
#define GF   64      // filters per group
#define NP   (BB*HH*WW)   // 131072 pixels

// Scratch: sampled field, [g][pixel][288]  (302 MB)
__device__ float g_samp[(size_t)GG * NP * SCH];

// ---------------------------------------------------------------------------
// Kernel 1: offset conv + bilinear sampling.
// One warp per (pixel, group). lane = channel (0..31).
// Offset weights staged in smem as [tap][chan][j] padded to 20 -> LDS.128.
// ---------------------------------------------------------------------------
__global__ __launch_bounds__(256) void k_sample(
    const float* __restrict__ x,      // [B,H,W,64]
    const float* __restrict__ off_w,  // [G,3,3,32,18]
    const float* __restrict__ off_b)  // [G,18]
{
    __shared__ float ws[9 * 32 * 20];   // [t][c][j(pad 20)]
    __shared__ float wb[18];

    const int g   = blockIdx.y;
    const int tid = threadIdx.x;

    for (int i = tid; i < 9 * 32 * 20; i += 256) {
        int r = i / 20, j = i % 20;               // r = t*32 + c
        ws[i] = (j < 18) ? off_w[(size_t)(g * 288 + r) * 18 + j] : 0.f;
    }
    if (tid < 18) wb[tid] = off_b[g * 18 + tid];
    __syncthreads();

    const int warp = tid >> 5, lane = tid & 31;
    const int p   = blockIdx.x * 8 + warp;         // pixel index
    const int b   = p >> 14;
    const int rem = p & 16383;
    const int yy  = rem >> 7;
    const int xx  = rem & 127;

    // 3x3 neighborhood of this pixel, channel = lane (coalesced loads)
    float xv[9];
#pragma unroll
    for (int t = 0; t < 9; t++) {
        int ny = yy + t / 3 - 1, nx = xx + t % 3 - 1;
        xv[t] = (ny >= 0 && ny < HH && nx >= 0 && nx < WW)
              ? x[((size_t)((b * HH + ny) * WW + nx)) * CIN + g * GCH + lane]
              : 0.f;
    }

    // Offset conv: per-lane partials (this lane's channel), vectorized weights
    float po[20];
#pragma unroll
    for (int j = 0; j < 20; j++) po[j] = 0.f;
#pragma unroll
    for (int t = 0; t < 9; t++) {
        const float v = xv[t];
        const float4* wv = (const float4*)&ws[(t * 32 + lane) * 20];
#pragma unroll
        for (int q = 0; q < 5; q++) {
            float4 w = wv[q];
            po[q * 4 + 0] = fmaf(v, w.x, po[q * 4 + 0]);
            po[q * 4 + 1] = fmaf(v, w.y, po[q * 4 + 1]);
            po[q * 4 + 2] = fmaf(v, w.z, po[q * 4 + 2]);
            po[q * 4 + 3] = fmaf(v, w.w, po[q * 4 + 3]);
        }
    }
#pragma unroll
    for (int s = 16; s > 0; s >>= 1) {
#pragma unroll
        for (int j = 0; j < 18; j++)
            po[j] += __shfl_xor_sync(0xffffffffu, po[j], s);
    }
#pragma unroll
    for (int j = 0; j < 18; j++) po[j] += wb[j];

    // 9 bilinear samples, channel = lane. Replicate reference's clip/floor math
    // exactly (including the zero-result edge case at coord == 127.0).
    const size_t xbase = (size_t)b * (HH * WW) * CIN + g * GCH + lane;
    float* outp = &g_samp[((size_t)g * NP + p) * SCH + lane];
#pragma unroll
    for (int k = 0; k < 9; k++) {
        float lx = (float)xx + (float)(k % 3 - 1) + po[2 * k];
        float ly = (float)yy + (float)(k / 3 - 1) + po[2 * k + 1];
        lx = fminf(fmaxf(lx, 0.f), 127.f);
        ly = fminf(fmaxf(ly, 0.f), 127.f);
        float x0f = fminf(fmaxf(floorf(lx), 0.f), 127.f);
        float y0f = fminf(fmaxf(floorf(ly), 0.f), 127.f);
        float x1f = fminf(x0f + 1.f, 127.f);
        float y1f = fminf(y0f + 1.f, 127.f);
        int x0 = (int)x0f, x1 = (int)x1f, y0 = (int)y0f, y1 = (int)y1f;
        float dx1 = x1f - lx, dx0 = lx - x0f;
        float dy1 = y1f - ly, dy0 = ly - y0f;
        float Ia = x[xbase + (size_t)(y0 * WW + x0) * CIN];   // (y0,x0)
        float Ib = x[xbase + (size_t)(y1 * WW + x0) * CIN];   // (y1,x0)
        float Ic = x[xbase + (size_t)(y0 * WW + x1) * CIN];   // (y0,x1)
        float Id = x[xbase + (size_t)(y1 * WW + x1) * CIN];   // (y1,x1)
        outp[k * 32] = dx1 * dy1 * Ia + dx1 * dy0 * Ib
                     + dx0 * dy1 * Ic + dx0 * dy0 * Id;
    }
}

// ---------------------------------------------------------------------------
// Kernel 2: fused depthwise(3x3, groups=288) + pointwise(288->64).
// One block per 8x8 pixel tile per (b,g). 512 threads, __launch_bounds__(512,2).
// Channels processed in 3 chunks of 96 so smem = 92KB -> 2 blocks/SM.
// ---------------------------------------------------------------------------
#define CHUNK     96
#define NCHUNK    3
#define C4        (CHUNK/4)          // 24 float4 per pixel per chunk
#define SM_HALO   (100 * CHUNK)      // 9600 floats
#define SM_Y      (64 * CHUNK)       // 6144 floats
#define SM_PW     (64 * 100)         // 6400 floats ([f][c] padded to 100)
#define SM_DW     (9 * CHUNK)        // 864 floats
#define SM_FLOATS (SM_HALO + SM_Y + SM_PW + SM_DW)
#define SM_BYTES  (SM_FLOATS * 4)

__global__ __launch_bounds__(512, 2) void k_dwpw(
    const float* __restrict__ dw_w,   // [G,3,3,288,1]
    const float* __restrict__ dw_b,   // [G,288]
    const float* __restrict__ pw_w,   // [G,1,1,288,64]
    const float* __restrict__ pw_b,   // [G,64]
    float* __restrict__ out)          // [B,H,W,128]
{
    extern __shared__ float smem[];
    float* s_halo = smem;
    float* s_y    = smem + SM_HALO;
    float* s_pw   = smem + SM_HALO + SM_Y;
    float* s_dw   = smem + SM_HALO + SM_Y + SM_PW;

    const int tid = threadIdx.x;
    const int z   = blockIdx.z;
    const int g   = z & 1;
    const int b   = z >> 1;
    const int ty0 = blockIdx.y * 8;
    const int tx0 = blockIdx.x * 8;

    // pw phase mapping: 2 filters (fA, fA+32) x 4 pixels per thread
    const int fA = tid & 31;
    const int pq = tid >> 5;           // warp id 0..15 -> pixels pq*4..pq*4+3

    float accA[4], accB[4];
    {
        const float ba = __ldg(&pw_b[g * GF + fA]);
        const float bb = __ldg(&pw_b[g * GF + fA + 32]);
#pragma unroll
        for (int i = 0; i < 4; i++) { accA[i] = ba; accB[i] = bb; }
    }

    float4* t4 = (float4*)s_halo;
    float4* y4 = (float4*)s_y;
    float4* d4 = (float4*)s_dw;

    for (int cc = 0; cc < NCHUNK; cc++) {
        const int cbase = cc * CHUNK;
        __syncthreads();   // previous chunk's consumers done before overwrite

        // --- stage halo chunk: 100 px x 24 float4 ---
        for (int i = tid; i < 100 * C4; i += 512) {
            int hp = i / C4, c4 = i % C4;
            int hy = ty0 + hp / 10 - 1, hx = tx0 + hp % 10 - 1;
            float4 v = make_float4(0.f, 0.f, 0.f, 0.f);
            if (hy >= 0 && hy < HH && hx >= 0 && hx < WW)
                v = *(const float4*)&g_samp[((size_t)g * NP +
                        (size_t)((b * HH + hy) * WW + hx)) * SCH + cbase + c4 * 4];
            t4[i] = v;
        }
        // --- stage dw chunk: 9 x 24 float4 ---
        for (int i = tid; i < 9 * C4; i += 512) {
            int t = i / C4, c4 = i % C4;
            d4[i] = __ldg((const float4*)&dw_w[(size_t)g * 2592 + t * SCH
                                               + cbase + c4 * 4]);
        }
        // --- stage pw chunk, transposed to [f][c] with pad 100 ---
        for (int i = tid; i < CHUNK * 64; i += 512) {
            int c = i >> 6, f = i & 63;
            s_pw[f * 100 + c] =
                pw_w[(size_t)g * (SCH * GF) + (size_t)(cbase + c) * 64 + f];
        }
        __syncthreads();

        // --- depthwise 3x3 for this chunk ---
        for (int i = tid; i < 64 * C4; i += 512) {
            int p = i / C4, c4 = i % C4;
            int py = p >> 3, px = p & 7;
            float4 acc = __ldg((const float4*)&dw_b[g * SCH + cbase + c4 * 4]);
#pragma unroll
            for (int t = 0; t < 9; t++) {
                float4 w = d4[t * C4 + c4];
                float4 v = t4[((py + t / 3) * 10 + (px + t % 3)) * C4 + c4];
                acc.x = fmaf(w.x, v.x, acc.x);
                acc.y = fmaf(w.y, v.y, acc.y);
                acc.z = fmaf(w.z, v.z, acc.z);
                acc.w = fmaf(w.w, v.w, acc.w);
            }
            y4[i] = acc;
        }
        __syncthreads();

        // --- pointwise accumulate over this chunk ---
#pragma unroll 4
        for (int c4 = 0; c4 < C4; c4++) {
            float4 wa = *(const float4*)&s_pw[fA * 100 + c4 * 4];
            float4 wbv = *(const float4*)&s_pw[(fA + 32) * 100 + c4 * 4];
#pragma unroll
            for (int i = 0; i < 4; i++) {
                float4 yv = y4[(pq * 4 + i) * C4 + c4];   // broadcast in warp
                accA[i] = fmaf(yv.x, wa.x, accA[i]);
                accA[i] = fmaf(yv.y, wa.y, accA[i]);
                accA[i] = fmaf(yv.z, wa.z, accA[i]);
                accA[i] = fmaf(yv.w, wa.w, accA[i]);
                accB[i] = fmaf(yv.x, wbv.x, accB[i]);
                accB[i] = fmaf(yv.y, wbv.y, accB[i]);
                accB[i] = fmaf(yv.z, wbv.z, accB[i]);
                accB[i] = fmaf(yv.w, wbv.w, accB[i]);
            }
        }
    }

#pragma unroll
    for (int i = 0; i < 4; i++) {
        int p = pq * 4 + i;
        int py = p >> 3, px = p & 7;
        size_t o = ((size_t)((b * HH + ty0 + py) * WW) + tx0 + px) * (GG * GF)
                   + g * GF;
        out[o + fA]      = accA[i];
        out[o + fA + 32] = accB[i];
    }
}

// ---------------------------------------------------------------------------
extern "C" void kernel_launch(void* const* d_in, const int* in_sizes, int n_in,
                              void* d_out, int out_size)
{
    const float* x     = (const float*)d_in[0];
    const float* off_w = (const float*)d_in[1];
    const float* off_b = (const float*)d_in[2];
    const float* dw_w  = (const float*)d_in[3];
    const float* dw_b  = (const float*)d_in[4];
    const float* pw_w  = (const float*)d_in[5];
    const float* pw_b  = (const float*)d_in[6];
    float* out = (float*)d_out;

    cudaFuncSetAttribute(k_dwpw, cudaFuncAttributeMaxDynamicSharedMemorySize,
                         SM_BYTES);

    k_sample<<<dim3(NP / 8, GG), 256>>>(x, off_w, off_b);
    k_dwpw<<<dim3(WW / 8, HH / 8, BB * GG), 512, SM_BYTES>>>(
        dw_w, dw_b, pw_w, pw_b, out);
}

// round 3
// speedup vs baseline: 1.4887x; 1.3216x over previous
#include <cuda_runtime.h>
#include <cuda_bf16.h>
#include <math.h>

// Problem constants
#define BB   8
#define HH   128
#define WW   128
#define CIN  64
#define GG   2
#define GCH  32      // channels per group
#define SCH  288     // K*K*GC
#define GF   64      // filters per group
#define NP   (BB*HH*WW)   // 131072 pixels

// Scratch
__device__ float g_samp[(size_t)GG * NP * SCH];   // sampled field   (302 MB)
__device__ float g_off [(size_t)GG * NP * 18];    // offsets         (19 MB)

// ===========================================================================
// Kernel 0: offset conv (3x3, 32 -> 18) per group. Thread-per-pixel, 16x16
// tile per block, x tile + weights in smem.
// ===========================================================================
#define OT 16
#define OHT 18                    // tile + halo
#define XPS 33                    // padded position stride (floats)
#define OFF_XT   (OHT*OHT*XPS)    // 10692
#define OFF_WS   5760             // 9*32*20
#define OFF_WB   32
#define OFF_SOFF (OT*OT*18)       // 4608
#define OFF_SMEM_BYTES ((OFF_XT + OFF_WS + OFF_WB + OFF_SOFF) * 4)

__global__ __launch_bounds__(256, 2) void k_offsets(
    const float* __restrict__ x,      // [B,H,W,64]
    const float* __restrict__ off_w,  // [G,3,3,32,18]
    const float* __restrict__ off_b)  // [G,18]
{
    extern __shared__ float sm0[];
    float* xt   = sm0;
    float* ws   = sm0 + OFF_XT;
    float* wb   = sm0 + OFF_XT + OFF_WS;
    float* soff = sm0 + OFF_XT + OFF_WS + OFF_WB;

    const int tid = threadIdx.x;
    const int z   = blockIdx.z;           // b*2+g
    const int g   = z & 1;
    const int b   = z >> 1;
    const int ty0 = blockIdx.y * OT;
    const int tx0 = blockIdx.x * OT;

    // stage weights [t][c][j pad 20]
    for (int i = tid; i < OFF_WS; i += 256) {
        int r = i / 20, j = i % 20;
        ws[i] = (j < 18) ? off_w[(size_t)(g * 288 + r) * 18 + j] : 0.f;
    }
    if (tid < 18) wb[tid] = off_b[g * 18 + tid];

    // stage x tile 18x18x32 (origin at (-1,-1))
    for (int i = tid; i < OHT * OHT * 32; i += 256) {
        int pos = i >> 5, c = i & 31;
        int hy = ty0 + pos / OHT - 1, hx = tx0 + pos % OHT - 1;
        float v = 0.f;
        if (hy >= 0 && hy < HH && hx >= 0 && hx < WW)
            v = x[((size_t)((b * HH + hy) * WW + hx)) * CIN + g * GCH + c];
        xt[pos * XPS + c] = v;
    }
    __syncthreads();

    const int px = tid & 15, py = tid >> 4;
    float acc[20];
#pragma unroll
    for (int j = 0; j < 20; j++) acc[j] = 0.f;

#pragma unroll
    for (int t = 0; t < 9; t++) {
        const int pos0 = ((py + t / 3) * OHT + (px + t % 3)) * XPS;
        const float* wr = &ws[t * 32 * 20];
#pragma unroll 4
        for (int c = 0; c < 32; c++) {
            const float v = xt[pos0 + c];
            const float4* wv = (const float4*)&wr[c * 20];
#pragma unroll
            for (int q = 0; q < 5; q++) {
                float4 w = wv[q];
                acc[q*4+0] = fmaf(v, w.x, acc[q*4+0]);
                acc[q*4+1] = fmaf(v, w.y, acc[q*4+1]);
                acc[q*4+2] = fmaf(v, w.z, acc[q*4+2]);
                acc[q*4+3] = fmaf(v, w.w, acc[q*4+3]);
            }
        }
    }
#pragma unroll
    for (int j = 0; j < 18; j++)
        soff[(py * 16 + px) * 18 + j] = acc[j] + wb[j];
    __syncthreads();

    // coalesced write: each tile row = 16 px * 18 = 288 contiguous floats
    const size_t pbase = (size_t)b * (HH * WW) + (size_t)ty0 * WW + tx0;
    for (int i = tid; i < OT * OT * 18; i += 256) {
        int row = i / 288, rem = i % 288;
        g_off[((size_t)g * NP + pbase + (size_t)row * WW) * 18 + rem] = soff[i];
    }
}

// ===========================================================================
// Kernel 1: bilinear sampling. One warp per (pixel, group). lane = channel.
// ===========================================================================
__global__ __launch_bounds__(256) void k_sample(
    const float* __restrict__ x)      // [B,H,W,64]
{
    const int tid  = threadIdx.x;
    const int g    = blockIdx.y;
    const int warp = tid >> 5, lane = tid & 31;
    const int p   = blockIdx.x * 8 + warp;
    const int b   = p >> 14;
    const int rem = p & 16383;
    const int yy  = rem >> 7;
    const int xx  = rem & 127;

    // load 18 offsets (lane j holds off[j]); broadcast via shfl per sample
    float offv = 0.f;
    if (lane < 18) offv = g_off[((size_t)g * NP + p) * 18 + lane];

    const size_t xbase = (size_t)b * (HH * WW) * CIN + g * GCH + lane;
    float* outp = &g_samp[((size_t)g * NP + p) * SCH + lane];
#pragma unroll
    for (int k = 0; k < 9; k++) {
        float ox = __shfl_sync(0xffffffffu, offv, 2 * k);
        float oy = __shfl_sync(0xffffffffu, offv, 2 * k + 1);
        float lx = (float)xx + (float)(k % 3 - 1) + ox;
        float ly = (float)yy + (float)(k / 3 - 1) + oy;
        lx = fminf(fmaxf(lx, 0.f), 127.f);
        ly = fminf(fmaxf(ly, 0.f), 127.f);
        float x0f = fminf(fmaxf(floorf(lx), 0.f), 127.f);
        float y0f = fminf(fmaxf(floorf(ly), 0.f), 127.f);
        float x1f = fminf(x0f + 1.f, 127.f);
        float y1f = fminf(y0f + 1.f, 127.f);
        int x0 = (int)x0f, x1 = (int)x1f, y0 = (int)y0f, y1 = (int)y1f;
        float dx1 = x1f - lx, dx0 = lx - x0f;
        float dy1 = y1f - ly, dy0 = ly - y0f;
        float Ia = x[xbase + (size_t)(y0 * WW + x0) * CIN];
        float Ib = x[xbase + (size_t)(y1 * WW + x0) * CIN];
        float Ic = x[xbase + (size_t)(y0 * WW + x1) * CIN];
        float Id = x[xbase + (size_t)(y1 * WW + x1) * CIN];
        outp[k * 32] = dx1 * dy1 * Ia + dx1 * dy0 * Ib
                     + dx0 * dy1 * Ic + dx0 * dy0 * Id;
    }
}

// ===========================================================================
// Kernel 2: fused depthwise(3x3, groups=288) + pointwise(288->64).
// 8x8 tile per (b,g), 512 threads, 3 channel chunks of 96.
// dw: 2x1 pixel-pair register blocking. pw: split-K, 4f x 4px x 16 accs/thread.
// ===========================================================================
#define CHUNK  96
#define C4     24                 // float4 per pixel per chunk
#define YP4    25                 // y row pad (float4)
#define SM_HALO (100 * CHUNK)     // 9600 floats
#define SM_Y    (64 * YP4 * 4)    // 6400 floats
#define SM_PW   (64 * 100)        // 6400 floats [f][c pad 100]
#define SM_DW   (9 * CHUNK)       // 864 floats
#define SM_BYTES ((SM_HALO + SM_Y + SM_PW + SM_DW) * 4)
#define OUTP    68                // out staging row pad (floats)

__global__ __launch_bounds__(512, 2) void k_dwpw(
    const float* __restrict__ dw_w,   // [G,3,3,288,1]
    const float* __restrict__ dw_b,   // [G,288]
    const float* __restrict__ pw_w,   // [G,1,1,288,64]
    const float* __restrict__ pw_b,   // [G,64]
    float* __restrict__ out)          // [B,H,W,128]
{
    extern __shared__ float smem[];
    float* s_halo = smem;
    float* s_y    = smem + SM_HALO;
    float* s_pw   = smem + SM_HALO + SM_Y;
    float* s_dw   = smem + SM_HALO + SM_Y + SM_PW;
    // post-loop aliases (y/halo/pw all dead by then)
    float* s_red  = s_pw;                 // 4096 floats
    float* s_out  = s_halo;               // 64*68 = 4352 floats

    const int tid = threadIdx.x;
    const int z   = blockIdx.z;
    const int g   = z & 1;
    const int b   = z >> 1;
    const int ty0 = blockIdx.y * 8;
    const int tx0 = blockIdx.x * 8;

    // pw mapping: team 0/1 (even/odd c4), 4 filters x 4 pixels per thread
    const int team = tid >> 8;
    const int r    = tid & 255;
    const int fq   = r >> 4;       // 0..15
    const int pq   = r & 15;       // 0..15
    const int fb   = fq * 4;

    float acc[16];
#pragma unroll
    for (int i = 0; i < 16; i++) acc[i] = 0.f;

    float4* t4  = (float4*)s_halo;
    float4* y4p = (float4*)s_y;
    float4* d4  = (float4*)s_dw;

    for (int cc = 0; cc < 3; cc++) {
        const int cbase = cc * CHUNK;
        __syncthreads();

        // stage halo: 100 px x 24 float4
        for (int i = tid; i < 100 * C4; i += 512) {
            int hp = i / C4, c4 = i % C4;
            int hy = ty0 + hp / 10 - 1, hx = tx0 + hp % 10 - 1;
            float4 v = make_float4(0.f, 0.f, 0.f, 0.f);
            if (hy >= 0 && hy < HH && hx >= 0 && hx < WW)
                v = *(const float4*)&g_samp[((size_t)g * NP +
                        (size_t)((b * HH + hy) * WW + hx)) * SCH + cbase + c4 * 4];
            t4[i] = v;
        }
        for (int i = tid; i < 9 * C4; i += 512) {
            int t = i / C4, c4 = i % C4;
            d4[i] = __ldg((const float4*)&dw_w[(size_t)g * 2592 + t * SCH
                                               + cbase + c4 * 4]);
        }
        // pw weights transposed to [f][c pad 100]
        for (int i = tid; i < CHUNK * 64; i += 512) {
            int c = i >> 6, f = i & 63;
            s_pw[f * 100 + c] =
                pw_w[(size_t)g * (SCH * GF) + (size_t)(cbase + c) * 64 + f];
        }
        __syncthreads();

        // depthwise: 2x1 pixel pairs. 768 items
        for (int i = tid; i < 768; i += 512) {
            int c4 = i % C4;
            int pair = i / C4;                 // 0..31
            int py = pair >> 2, qx = (pair & 3) * 2;
            float4 bias = __ldg((const float4*)&dw_b[g * SCH + cbase + c4 * 4]);
            float4 a0 = bias, a1 = bias;
#pragma unroll
            for (int ty = 0; ty < 3; ty++) {
                const float4* vr = &t4[((py + ty) * 10 + qx) * C4 + c4];
                float4 v0 = vr[0], v1 = vr[C4], v2 = vr[2*C4], v3 = vr[3*C4];
                float4 w0 = d4[(ty*3+0)*C4 + c4];
                float4 w1 = d4[(ty*3+1)*C4 + c4];
                float4 w2 = d4[(ty*3+2)*C4 + c4];
                a0.x = fmaf(w0.x,v0.x,fmaf(w1.x,v1.x,fmaf(w2.x,v2.x,a0.x)));
                a0.y = fmaf(w0.y,v0.y,fmaf(w1.y,v1.y,fmaf(w2.y,v2.y,a0.y)));
                a0.z = fmaf(w0.z,v0.z,fmaf(w1.z,v1.z,fmaf(w2.z,v2.z,a0.z)));
                a0.w = fmaf(w0.w,v0.w,fmaf(w1.w,v1.w,fmaf(w2.w,v2.w,a0.w)));
                a1.x = fmaf(w0.x,v1.x,fmaf(w1.x,v2.x,fmaf(w2.x,v3.x,a1.x)));
                a1.y = fmaf(w0.y,v1.y,fmaf(w1.y,v2.y,fmaf(w2.y,v3.y,a1.y)));
                a1.z = fmaf(w0.z,v1.z,fmaf(w1.z,v2.z,fmaf(w2.z,v3.z,a1.z)));
                a1.w = fmaf(w0.w,v1.w,fmaf(w1.w,v2.w,fmaf(w2.w,v3.w,a1.w)));
            }
            y4p[(py * 8 + qx) * YP4 + c4]     = a0;
            y4p[(py * 8 + qx + 1) * YP4 + c4] = a1;
        }
        __syncthreads();

        // pointwise accumulate: this team's c4 slice (even/odd)
#pragma unroll 3
        for (int s = 0; s < C4; s += 2) {
            const int c4 = s + team;
            float4 y0 = y4p[(pq +  0) * YP4 + c4];
            float4 y1 = y4p[(pq + 16) * YP4 + c4];
            float4 y2 = y4p[(pq + 32) * YP4 + c4];
            float4 y3 = y4p[(pq + 48) * YP4 + c4];
#pragma unroll
            for (int k = 0; k < 4; k++) {
                float4 w = *(const float4*)&s_pw[(fb + k) * 100 + c4 * 4];
                acc[k*4+0] = fmaf(y0.x,w.x,fmaf(y0.y,w.y,fmaf(y0.z,w.z,fmaf(y0.w,w.w,acc[k*4+0]))));
                acc[k*4+1] = fmaf(y1.x,w.x,fmaf(y1.y,w.y,fmaf(y1.z,w.z,fmaf(y1.w,w.w,acc[k*4+1]))));
                acc[k*4+2] = fmaf(y2.x,w.x,fmaf(y2.y,w.y,fmaf(y2.z,w.z,fmaf(y2.w,w.w,acc[k*4+2]))));
                acc[k*4+3] = fmaf(y3.x,w.x,fmaf(y3.y,w.y,fmaf(y3.z,w.z,fmaf(y3.w,w.w,acc[k*4+3]))));
            }
        }
    }
    __syncthreads();

    // split-K reduce: team1 -> smem
    if (team == 1) {
#pragma unroll
        for (int i = 0; i < 16; i++) s_red[r * 16 + i] = acc[i];
    }
    __syncthreads();

    if (team == 0) {
#pragma unroll
        for (int k = 0; k < 4; k++) {
            const float bias = __ldg(&pw_b[g * GF + fb + k]);
#pragma unroll
            for (int i = 0; i < 4; i++) {
                int p = pq + 16 * i;
                s_out[p * OUTP + fb + k] = acc[k*4+i] + s_red[r*16 + k*4+i] + bias;
            }
        }
    }
    __syncthreads();

    // coalesced store
    for (int i = tid; i < 4096; i += 512) {
        int p = i >> 6, f = i & 63;
        int py = p >> 3, px = p & 7;
        out[((size_t)((b * HH + ty0 + py) * WW) + tx0 + px) * (GG * GF)
            + g * GF + f] = s_out[p * OUTP + f];
    }
}

// ---------------------------------------------------------------------------
extern "C" void kernel_launch(void* const* d_in, const int* in_sizes, int n_in,
                              void* d_out, int out_size)
{
    const float* x     = (const float*)d_in[0];
    const float* off_w = (const float*)d_in[1];
    const float* off_b = (const float*)d_in[2];
    const float* dw_w  = (const float*)d_in[3];
    const float* dw_b  = (const float*)d_in[4];
    const float* pw_w  = (const float*)d_in[5];
    const float* pw_b  = (const float*)d_in[6];
    float* out = (float*)d_out;

    cudaFuncSetAttribute(k_offsets, cudaFuncAttributeMaxDynamicSharedMemorySize,
                         OFF_SMEM_BYTES);
    cudaFuncSetAttribute(k_dwpw, cudaFuncAttributeMaxDynamicSharedMemorySize,
                         SM_BYTES);

    k_offsets<<<dim3(WW/OT, HH/OT, BB*GG), 256, OFF_SMEM_BYTES>>>(x, off_w, off_b);
    k_sample<<<dim3(NP / 8, GG), 256>>>(x);
    k_dwpw<<<dim3(WW / 8, HH / 8, BB * GG), 512, SM_BYTES>>>(
        dw_w, dw_b, pw_w, pw_b, out);
}